// round 16
// baseline (speedup 1.0000x reference)
#include <cuda_runtime.h>
#include <math.h>

#define BB   8
#define PP   4096
#define NN   (BB*PP)
#define KK   20
#define LL   10
#define FF   32
#define KSS  5
#define NCLS 40
#define R24  24

// -------- persistent scratch --------
__device__ float4 g_p4[NN];         // batch-sorted-by-x (x,y,z,bits(origid))
__device__ float  g_node[NN*FF];
__device__ float  g_v3[NN*3];
__device__ double g_acc[2*FF];      // [0..31] sum, [32..63] sumsq
__device__ float  g_ys[R24*FF];

// ---------------- power iteration (matches jax exactly) ----------------
__device__ __forceinline__ void power_iter(
    float m00, float m01, float m02, float m11, float m12, float m22,
    float &vx, float &vy, float &vz, float &lam)
{
    float x = 0.57735026918962576f, y = x, z = x;
    #pragma unroll
    for (int it = 0; it < 5; ++it) {
        float wx = m00*x + m01*y + m02*z;
        float wy = m01*x + m11*y + m12*z;
        float wz = m02*x + m12*y + m22*z;
        float nr = sqrtf(wx*wx + wy*wy + wz*wz);
        float inv = 1.0f / (nr + 1e-12f);
        x = wx*inv; y = wy*inv; z = wz*inv;
    }
    float wx = m00*x + m01*y + m02*z;
    float wy = m01*x + m11*y + m12*z;
    float wz = m02*x + m12*y + m22*z;
    lam = x*wx + y*wy + z*wz;
    vx = x; vy = y; vz = z;
}

// ---------------- kernel 0: per-batch bitonic sort by x ----------------
__global__ void __launch_bounds__(1024) k_sort(const float* __restrict__ pos)
{
    __shared__ unsigned long long sk[PP];
    int b = blockIdx.x, tid = threadIdx.x;
    const float* pb = pos + (size_t)b*PP*3;

    if (b == 0 && tid < 64) g_acc[tid] = 0.0;   // zero stats accumulators

    for (int i = tid; i < PP; i += 1024) {
        unsigned u = __float_as_uint(pb[i*3]);
        u = (u & 0x80000000u) ? ~u : (u | 0x80000000u);   // order-preserving key
        sk[i] = ((unsigned long long)u << 32) | (unsigned)i;
    }
    __syncthreads();

    for (int k = 2; k <= PP; k <<= 1) {
        for (int j = k >> 1; j > 0; j >>= 1) {
            for (int t = tid; t < PP; t += 1024) {
                int ixj = t ^ j;
                if (ixj > t) {
                    bool asc = ((t & k) == 0);
                    unsigned long long a = sk[t], c = sk[ixj];
                    bool sw = asc ? (a > c) : (a < c);
                    if (sw) { sk[t] = c; sk[ixj] = a; }
                }
            }
            __syncthreads();
        }
    }

    for (int i = tid; i < PP; i += 1024) {
        int oid = (int)(sk[i] & 0xFFFFFFFFu);
        g_p4[b*PP + i] = make_float4(pb[oid*3+0], pb[oid*3+1], pb[oid*3+2],
                                     __uint_as_float((unsigned)oid));
    }
}

// ---------------- kernel 1: FUSED exact pruned KNN + eig + spline conv -------
// grid: 8 batches x 32 chunks = 256 blocks, 128 threads
// dyn smem: sp4 (64K) + regionB (21504: isort then basis rows) + swW (16000)
__global__ void __launch_bounds__(128) k_main(
    const float* __restrict__ Wsp,
    const float* __restrict__ root,
    const float* __restrict__ bias)
{
    extern __shared__ char sm[];
    float4* sp4  = (float4*)sm;                    // [4096]
    int*    isort = (int*)(sm + 65536);            // [4096] (aliased by sbas later)
    float*  sbas  = (float*)(sm + 65536);          // rows tid*42 (after barrier)
    float4* swW   = (float4*)(sm + 87040);         // [1000]

    int b     = blockIdx.x >> 5;
    int chunk = blockIdx.x & 31;
    int tid   = threadIdx.x;
    int lane  = tid & 31;
    int wid   = tid >> 5;

    for (int i = tid; i < PP; i += 128) {
        float4 v = g_p4[b*PP + i];
        sp4[i] = v;
        isort[(int)__float_as_uint(v.w)] = i;     // inverse: orig -> sorted
    }
    const float4* Wsp4 = (const float4*)Wsp;
    for (int i = tid; i < 125*8; i += 128) swW[i] = Wsp4[i];
    __syncthreads();

    // =================== phase 1: exact pruned top-20 (per warp) =============
    int wq = chunk*128 + wid*32;          // warp's first query (sorted index)
    int me = wq + lane;
    float4 q = sp4[me];
    float qx = q.x, qy = q.y, qz = q.z;

    unsigned long long top[KK];
    #pragma unroll
    for (int s = 0; s < KK; ++s) top[s] = ~0ull;

#define GROUP8(J0, JEND) {                                                      \
    unsigned long long pp[8];                                                   \
    _Pragma("unroll")                                                           \
    for (int u = 0; u < 8; ++u) {                                               \
        int j = (J0) + u;                                                       \
        bool valid = (j < (JEND)) && (j != me);                                 \
        float4 c = sp4[j];                                                      \
        float dx = c.x-qx, dy = c.y-qy, dz = c.z-qz;                            \
        float d  = fmaf(dz, dz, fmaf(dy, dy, dx*dx));                           \
        unsigned long long pk =                                                 \
            ((unsigned long long)__float_as_uint(d) << 32) |                    \
            (unsigned)__float_as_uint(c.w);                                     \
        pp[u] = valid ? pk : ~0ull;                                             \
    }                                                                           \
    unsigned long long m = pp[0];                                               \
    _Pragma("unroll")                                                           \
    for (int u = 1; u < 8; ++u) m = (pp[u] < m) ? pp[u] : m;                    \
    while (__any_sync(0xFFFFFFFFu, m < top[KK-1])) {                            \
        if (m < top[KK-1]) {                                                    \
            int su = 7;                                                         \
            if (pp[6] == m) su = 6;                                             \
            if (pp[5] == m) su = 5;                                             \
            if (pp[4] == m) su = 4;                                             \
            if (pp[3] == m) su = 3;                                             \
            if (pp[2] == m) su = 2;                                             \
            if (pp[1] == m) su = 1;                                             \
            if (pp[0] == m) su = 0;                                             \
            _Pragma("unroll")                                                   \
            for (int u = 0; u < 8; ++u) if (u == su) pp[u] = ~0ull;             \
            int r = 0;                                                          \
            _Pragma("unroll")                                                   \
            for (int s = 0; s < KK-1; ++s) r += (top[s] <= m);                  \
            _Pragma("unroll")                                                   \
            for (int s = KK-1; s >= 0; --s) {                                   \
                bool sh = (s > r), eq = (s == r);                               \
                unsigned long long pd = (s > 0) ? top[s-1] : m;                 \
                top[s] = eq ? m : (sh ? pd : top[s]);                           \
            }                                                                   \
            m = pp[0];                                                          \
            _Pragma("unroll")                                                   \
            for (int u = 1; u < 8; ++u) m = (pp[u] < m) ? pp[u] : m;            \
        }                                                                       \
    } }

    int istart = wq - 96;  if (istart < 0) istart = 0;
    int iend   = wq + 128; if (iend > PP) iend = PP;
    #pragma unroll 1
    for (int j0 = istart; j0 < iend; j0 += 8) GROUP8(j0, iend);

    int dlo = istart, uhi = iend;
    #pragma unroll 1
    while (true) {
        float d20 = __uint_as_float((unsigned)(top[KK-1] >> 32));
        bool dn_ok = true, up_ok = true;
        if (dlo > 0)  { float g = qx - sp4[dlo-1].x; dn_ok = (g*g > d20); }
        if (uhi < PP) { float g = sp4[uhi].x - qx;   up_ok = (g*g > d20); }
        if (__all_sync(0xFFFFFFFFu, dn_ok && up_ok)) break;

        if (!__all_sync(0xFFFFFFFFu, dn_ok) && dlo > 0) {
            int s = dlo - 32; if (s < 0) s = 0;
            #pragma unroll 1
            for (int j0 = s; j0 < dlo; j0 += 8) GROUP8(j0, dlo);
            dlo = s;
        }
        if (!__all_sync(0xFFFFFFFFu, up_ok) && uhi < PP) {
            int e = uhi + 32; if (e > PP) e = PP;
            #pragma unroll 1
            for (int j0 = uhi; j0 < e; j0 += 8) GROUP8(j0, e);
            uhi = e;
        }
    }
#undef GROUP8

    // =================== phase 2: features (same block, no round trip) =======
    int n = b*PP + (int)__float_as_uint(q.w);      // original point id

    int nbs[KK];                                   // sorted-space neighbor idx
    #pragma unroll
    for (int s = 0; s < KK; ++s)
        nbs[s] = isort[(int)(top[s] & 0xFFFFFFFFu)];

    // ---- covariance over the 10 nearest ----
    float cxx=0,cxy=0,cxz=0,cyy=0,cyz=0,czz=0;
    #pragma unroll
    for (int l = 0; l < LL; ++l) {
        float4 c = sp4[nbs[l]];
        float dx = c.x-qx, dy = c.y-qy, dz = c.z-qz;
        cxx += dx*dx; cxy += dx*dy; cxz += dx*dz;
        cyy += dy*dy; cyz += dy*dz; czz += dz*dz;
    }

    float v1x,v1y,v1z,l1;
    power_iter(cxx,cxy,cxz,cyy,cyz,czz, v1x,v1y,v1z,l1);
    float m00 = cxx - l1*v1x*v1x, m01 = cxy - l1*v1x*v1y, m02 = cxz - l1*v1x*v1z;
    float m11 = cyy - l1*v1y*v1y, m12 = cyz - l1*v1y*v1z, m22 = czz - l1*v1z*v1z;
    float v2x,v2y,v2z,l2;
    power_iter(m00,m01,m02,m11,m12,m22, v2x,v2y,v2z,l2);
    float v3x = v1y*v2z - v1z*v2y;
    float v3y = v1z*v2x - v1x*v2z;
    float v3z = v1x*v2y - v1y*v2x;
    float n3  = sqrtf(v3x*v3x + v3y*v3y + v3z*v3z);
    float i3  = 1.0f / (n3 + 1e-12f);
    v3x *= i3; v3y *= i3; v3z *= i3;

    // ---- pass A: sign and max-abs ----
    float ssum = 0.f, mx12 = 0.f, mx3 = 0.f;
    #pragma unroll
    for (int k = 0; k < KK; ++k) {
        float4 c = sp4[nbs[k]];
        float dx = c.x-qx, dy = c.y-qy, dz = c.z-qz;
        float d1 = dx*v1x + dy*v1y + dz*v1z;
        float d2 = dx*v2x + dy*v2y + dz*v2z;
        float d3 = dx*v3x + dy*v3y + dz*v3z;
        ssum += d3;
        mx12 = fmaxf(mx12, fmaxf(fabsf(d1), fabsf(d2)));
        mx3  = fmaxf(mx3, fabsf(d3));
    }
    float sgn    = (ssum > 0.f) ? 1.f : ((ssum < 0.f) ? -1.f : 0.f);
    float maxabs = (sgn != 0.f) ? fmaxf(mx12, mx3) : mx12;
    float rm     = 1.0f / maxabs;

    // all threads finished reading isort before it becomes basis scratch
    __syncthreads();

    // ---- pass B: dense-basis spline conv in 3 cell-range passes (42/42/41) --
    float msg[FF];
    #pragma unroll
    for (int f = 0; f < FF; ++f) msg[f] = 0.f;

    int off = tid*42;

    #pragma unroll 1
    for (int pass = 0; pass < 3; ++pass) {
        int lo    = pass*42;
        int width = (pass == 2) ? 41 : 42;

        for (int c = 0; c < 42; ++c) sbas[off + c] = 0.f;

        #pragma unroll 1
        for (int k = 0; k < KK; ++k) {
            float4 c = sp4[nbs[k]];
            float dx = c.x-qx, dy = c.y-qy, dz = c.z-qz;
            float d0 = dx*v1x + dy*v1y + dz*v1z;
            float d1 = dx*v2x + dy*v2y + dz*v2z;
            float d2 = (dx*v3x + dy*v3y + dz*v3z) * sgn;

            float vv0 = (d0*rm*0.5f + 0.5f)*4.f;
            float vv1 = (d1*rm*0.5f + 0.5f)*4.f;
            float vv2 = (d2*rm*0.5f + 0.5f)*4.f;
            float fl0 = floorf(vv0), fl1 = floorf(vv1), fl2 = floorf(vv2);
            float fr0 = vv0-fl0, fr1 = vv1-fl1, fr2 = vv2-fl2;
            int i0 = (int)fl0, i1 = (int)fl1, i2 = (int)fl2;

            int ia0 = min(max(i0,  0),4), ib0 = min(max(i0+1,0),4);
            int ia1 = min(max(i1,  0),4), ib1 = min(max(i1+1,0),4);
            int ia2 = min(max(i2,  0),4), ib2 = min(max(i2+1,0),4);
            float wa0 = 1.f-fr0, wb0 = fr0;
            float wa1 = 1.f-fr1, wb1 = fr1;
            float wa2 = 1.f-fr2, wb2 = fr2;

            #pragma unroll
            for (int s8 = 0; s8 < 8; ++s8) {
                int bit0 = (s8>>2)&1, bit1 = (s8>>1)&1, bit2 = s8&1;
                float bas = (bit0?wb0:wa0) * (bit1?wb1:wa1) * (bit2?wb2:wa2);
                int j0 = bit0?ib0:ia0, j1 = bit1?ib1:ia1, j2 = bit2?ib2:ia2;
                int cell = (j0*KSS + j1)*KSS + j2;
                int loc  = cell - lo;
                if (loc >= 0 && loc < width)
                    sbas[off + loc] += bas;
            }
        }

        #pragma unroll 4
        for (int c = 0; c < width; ++c) {
            float bb = sbas[off + c];
            int cell = lo + c;
            #pragma unroll
            for (int f4 = 0; f4 < 8; ++f4) {
                float4 w = swW[cell*8 + f4];
                msg[4*f4+0] += bb * w.x;
                msg[4*f4+1] += bb * w.y;
                msg[4*f4+2] += bb * w.z;
                msg[4*f4+3] += bb * w.w;
            }
        }
    }

    // ---- node output + fused batch-stat accumulation ----
    float keepS = 0.f, keepS2 = 0.f;
    #pragma unroll
    for (int f = 0; f < FF; ++f) {
        float v = msg[f] * (1.0f/(float)KK) + root[f] + bias[f];
        g_node[(size_t)n*FF + f] = v;
        float s = v, s2 = v*v;
        #pragma unroll
        for (int o2 = 16; o2; o2 >>= 1) {
            s  += __shfl_xor_sync(0xFFFFFFFFu, s,  o2);
            s2 += __shfl_xor_sync(0xFFFFFFFFu, s2, o2);
        }
        if (lane == f) { keepS = s; keepS2 = s2; }
    }
    g_v3[n*3+0] = v3x; g_v3[n*3+1] = v3y; g_v3[n*3+2] = v3z;

    __shared__ float blkS[4][FF], blkS2[4][FF];
    blkS[wid][lane] = keepS; blkS2[wid][lane] = keepS2;
    __syncthreads();
    if (wid == 0) {
        float tS  = blkS[0][lane]  + blkS[1][lane]  + blkS[2][lane]  + blkS[3][lane];
        float tS2 = blkS2[0][lane] + blkS2[1][lane] + blkS2[2][lane] + blkS2[3][lane];
        atomicAdd(&g_acc[lane],      (double)tS);
        atomicAdd(&g_acc[FF + lane], (double)tS2);
    }
}

// ---------------- kernel 2: BN-fold + sigmoid + reshape-mean (fin fused) ------
__global__ void k_ys(const float* __restrict__ gamma, const float* __restrict__ beta)
{
    __shared__ float sa[FF], sb[FF];
    int r = blockIdx.x >> 5;
    int j = blockIdx.x & 31;
    int tid = threadIdx.x;

    if (tid < FF) {
        double mu  = g_acc[tid] / (double)NN;
        double var = g_acc[FF+tid] / (double)NN - mu*mu;
        float istd = (float)(1.0 / sqrt(var + 1e-5));
        float a = gamma[tid] * istd;
        sa[tid] = a;
        sb[tid] = beta[tid] - (float)mu * a;
    }
    __syncthreads();

    float sum = 0.f;
    #pragma unroll 4
    for (int p = tid; p < PP; p += 128) {
        int flat = r*(PP*FF) + p*FF + j;
        int nn   = flat / 96;
        int rem  = flat - nn*96;
        int fch  = rem / 3;
        int c    = rem - fch*3;
        float x  = g_node[(size_t)nn*FF + fch];
        float xb = fmaf(sa[fch], x, sb[fch]);
        float o  = xb * g_v3[nn*3 + c];
        sum += __fdividef(1.f, 1.f + __expf(-o));
    }
    __shared__ float red[128];
    red[tid] = sum;
    __syncthreads();
    for (int off = 64; off; off >>= 1) {
        if (tid < off) red[tid] += red[tid+off];
        __syncthreads();
    }
    if (tid == 0) g_ys[r*FF + j] = red[0] / (float)PP;
}

// ---------------- kernel 3: MLP head + log_softmax (one block per row) --------
__global__ void k_head(
    const float* __restrict__ W1, const float* __restrict__ b1,
    const float* __restrict__ W2, const float* __restrict__ b2,
    float* __restrict__ out)
{
    __shared__ float ys[FF];
    __shared__ float y1[256];
    __shared__ float part[8][NCLS];
    __shared__ float zz[NCLS];
    __shared__ float s_lse;
    int r = blockIdx.x, tid = threadIdx.x;   // 320 threads

    if (tid < FF) ys[tid] = g_ys[r*FF + tid];
    __syncthreads();

    if (tid < 256) {
        float acc = b1[tid];
        #pragma unroll
        for (int f = 0; f < FF; ++f) acc = fmaf(ys[f], W1[f*256 + tid], acc);
        y1[tid] = acc > 0.f ? acc : expm1f(acc);
    }
    __syncthreads();

    {
        int c  = tid % NCLS;
        int sgm = tid / NCLS;     // 0..7
        float acc = 0.f;
        #pragma unroll
        for (int h = 0; h < 32; ++h) acc = fmaf(y1[sgm*32 + h], W2[(sgm*32+h)*NCLS + c], acc);
        part[sgm][c] = acc;
    }
    __syncthreads();

    if (tid < NCLS) {
        float acc = b2[tid];
        #pragma unroll
        for (int s = 0; s < 8; ++s) acc += part[s][tid];
        zz[tid] = acc;
    }
    __syncthreads();

    if (tid == 0) {
        float mx = -3.4e38f;
        for (int c = 0; c < NCLS; ++c) mx = fmaxf(mx, zz[c]);
        float se = 0.f;
        for (int c = 0; c < NCLS; ++c) se += expf(zz[c] - mx);
        s_lse = mx + logf(se);
    }
    __syncthreads();
    if (tid < NCLS) out[r*NCLS + tid] = zz[tid] - s_lse;
}

// ---------------- launch ----------------
extern "C" void kernel_launch(void* const* d_in, const int* in_sizes, int n_in,
                              void* d_out, int out_size)
{
    const float* pos   = (const float*)d_in[0];
    const float* Wsp   = (const float*)d_in[1];
    const float* root  = (const float*)d_in[2];
    const float* bias  = (const float*)d_in[3];
    const float* gamma = (const float*)d_in[4];
    const float* beta  = (const float*)d_in[5];
    const float* W1    = (const float*)d_in[6];
    const float* b1    = (const float*)d_in[7];
    const float* W2    = (const float*)d_in[8];
    const float* b2    = (const float*)d_in[9];
    float* out = (float*)d_out;

    size_t smem_main = 65536 + 21504 + 16000;    // 103,040 B -> 2 blocks/SM
    cudaFuncSetAttribute(k_main, cudaFuncAttributeMaxDynamicSharedMemorySize, (int)smem_main);

    k_sort <<<BB, 1024>>>(pos);
    k_main <<<BB*32, 128, smem_main>>>(Wsp, root, bias);
    k_ys   <<<R24*FF, 128>>>(gamma, beta);
    k_head <<<R24, 320>>>(W1, b1, W2, b2, out);
}

// round 17
// speedup vs baseline: 1.2065x; 1.2065x over previous
#include <cuda_runtime.h>
#include <math.h>

#define BB   8
#define PP   4096
#define NN   (BB*PP)
#define KK   20
#define LL   10
#define FF   32
#define KSS  5
#define NCLS 40
#define R24  24

// -------- persistent scratch --------
__device__ unsigned long long g_ku[KK*NN];  // packed (dist_bits<<32 | orig_idx), [slot][n]
__device__ float4 g_p4[NN];         // batch-sorted-by-x (x,y,z,bits(origid))
__device__ float  g_node[NN*FF];
__device__ float  g_v3[NN*3];
__device__ double g_acc[2*FF];      // [0..31] sum, [32..63] sumsq
__device__ float  g_ys[R24*FF];

// ---------------- power iteration (matches jax exactly) ----------------
__device__ __forceinline__ void power_iter(
    float m00, float m01, float m02, float m11, float m12, float m22,
    float &vx, float &vy, float &vz, float &lam)
{
    float x = 0.57735026918962576f, y = x, z = x;
    #pragma unroll
    for (int it = 0; it < 5; ++it) {
        float wx = m00*x + m01*y + m02*z;
        float wy = m01*x + m11*y + m12*z;
        float wz = m02*x + m12*y + m22*z;
        float nr = sqrtf(wx*wx + wy*wy + wz*wz);
        float inv = 1.0f / (nr + 1e-12f);
        x = wx*inv; y = wy*inv; z = wz*inv;
    }
    float wx = m00*x + m01*y + m02*z;
    float wy = m01*x + m11*y + m12*z;
    float wz = m02*x + m12*y + m22*z;
    lam = x*wx + y*wy + z*wz;
    vx = x; vy = y; vz = z;
}

// ---------------- kernel 0: per-batch bitonic sort by x ----------------
__global__ void __launch_bounds__(1024) k_sort(const float* __restrict__ pos)
{
    __shared__ unsigned long long sk[PP];
    int b = blockIdx.x, tid = threadIdx.x;
    const float* pb = pos + (size_t)b*PP*3;

    if (b == 0 && tid < 64) g_acc[tid] = 0.0;   // zero stats accumulators

    for (int i = tid; i < PP; i += 1024) {
        unsigned u = __float_as_uint(pb[i*3]);
        u = (u & 0x80000000u) ? ~u : (u | 0x80000000u);   // order-preserving key
        sk[i] = ((unsigned long long)u << 32) | (unsigned)i;
    }
    __syncthreads();

    for (int k = 2; k <= PP; k <<= 1) {
        for (int j = k >> 1; j > 0; j >>= 1) {
            for (int t = tid; t < PP; t += 1024) {
                int ixj = t ^ j;
                if (ixj > t) {
                    bool asc = ((t & k) == 0);
                    unsigned long long a = sk[t], c = sk[ixj];
                    bool sw = asc ? (a > c) : (a < c);
                    if (sw) { sk[t] = c; sk[ixj] = a; }
                }
            }
            __syncthreads();
        }
    }

    for (int i = tid; i < PP; i += 1024) {
        int oid = (int)(sk[i] & 0xFFFFFFFFu);
        g_p4[b*PP + i] = make_float4(pb[oid*3+0], pb[oid*3+1], pb[oid*3+2],
                                     __uint_as_float((unsigned)oid));
    }
}

// ---------------- kernel 1: exact pruned top-20, per-WARP expansion ----------
// grid: 8 batches x 32 chunks = 256 blocks, 128 threads
// dyn smem: float4 sp4[4096] = 65,536B  (3 blocks/SM)
__global__ void __launch_bounds__(128) k_knn()
{
    extern __shared__ float4 sp4[];     // [4096] (x,y,z,sid-bits)

    int b     = blockIdx.x >> 5;
    int chunk = blockIdx.x & 31;
    int tid   = threadIdx.x;
    int lane  = tid & 31;

    for (int i = tid; i < PP; i += 128) sp4[i] = g_p4[b*PP + i];
    __syncthreads();

    int wq = chunk*128 + (tid >> 5)*32;   // warp's first query (sorted index)
    int me = wq + lane;
    float4 q = sp4[me];
    float qx = q.x, qy = q.y, qz = q.z;

    unsigned long long top[KK];
    #pragma unroll
    for (int s = 0; s < KK; ++s) top[s] = ~0ull;

    // ---- batched 8-group scan with min-extraction insert (exact u64 keys) ----
#define GROUP8(J0, JEND) {                                                      \
    unsigned long long pp[8];                                                   \
    _Pragma("unroll")                                                           \
    for (int u = 0; u < 8; ++u) {                                               \
        int j = (J0) + u;                                                       \
        bool valid = (j < (JEND)) && (j != me);                                 \
        float4 c = sp4[j];                                                      \
        float dx = c.x-qx, dy = c.y-qy, dz = c.z-qz;                            \
        float d  = fmaf(dz, dz, fmaf(dy, dy, dx*dx));                           \
        unsigned long long pk =                                                 \
            ((unsigned long long)__float_as_uint(d) << 32) |                    \
            (unsigned)__float_as_uint(c.w);                                     \
        pp[u] = valid ? pk : ~0ull;                                             \
    }                                                                           \
    unsigned long long m = pp[0];                                               \
    _Pragma("unroll")                                                           \
    for (int u = 1; u < 8; ++u) m = (pp[u] < m) ? pp[u] : m;                    \
    while (__any_sync(0xFFFFFFFFu, m < top[KK-1])) {                            \
        if (m < top[KK-1]) {                                                    \
            int su = 7;                                                         \
            if (pp[6] == m) su = 6;                                             \
            if (pp[5] == m) su = 5;                                             \
            if (pp[4] == m) su = 4;                                             \
            if (pp[3] == m) su = 3;                                             \
            if (pp[2] == m) su = 2;                                             \
            if (pp[1] == m) su = 1;                                             \
            if (pp[0] == m) su = 0;                                             \
            _Pragma("unroll")                                                   \
            for (int u = 0; u < 8; ++u) if (u == su) pp[u] = ~0ull;             \
            int r = 0;                                                          \
            _Pragma("unroll")                                                   \
            for (int s = 0; s < KK-1; ++s) r += (top[s] <= m);                  \
            _Pragma("unroll")                                                   \
            for (int s = KK-1; s >= 0; --s) {                                   \
                bool sh = (s > r), eq = (s == r);                               \
                unsigned long long pd = (s > 0) ? top[s-1] : m;                 \
                top[s] = eq ? m : (sh ? pd : top[s]);                           \
            }                                                                   \
            m = pp[0];                                                          \
            _Pragma("unroll")                                                   \
            for (int u = 1; u < 8; ++u) m = (pp[u] < m) ? pp[u] : m;            \
        }                                                                       \
    } }

    // ---- phase 1: initial window around the warp's 32 queries ----
    int istart = wq - 96;  if (istart < 0) istart = 0;
    int iend   = wq + 128; if (iend > PP) iend = PP;
    #pragma unroll 1
    for (int j0 = istart; j0 < iend; j0 += 8) GROUP8(j0, iend);

    int dlo = istart, uhi = iend;

    // ---- phase 2: per-warp outward expansion with exact x-gap pruning ----
    #pragma unroll 1
    while (true) {
        float d20 = __uint_as_float((unsigned)(top[KK-1] >> 32));
        bool dn_ok = true, up_ok = true;
        if (dlo > 0)  { float g = qx - sp4[dlo-1].x; dn_ok = (g*g > d20); }
        if (uhi < PP) { float g = sp4[uhi].x - qx;   up_ok = (g*g > d20); }
        if (__all_sync(0xFFFFFFFFu, dn_ok && up_ok)) break;

        if (!__all_sync(0xFFFFFFFFu, dn_ok) && dlo > 0) {
            int s = dlo - 32; if (s < 0) s = 0;
            #pragma unroll 1
            for (int j0 = s; j0 < dlo; j0 += 8) GROUP8(j0, dlo);
            dlo = s;
        }
        if (!__all_sync(0xFFFFFFFFu, up_ok) && uhi < PP) {
            int e = uhi + 32; if (e > PP) e = PP;
            #pragma unroll 1
            for (int j0 = uhi; j0 < e; j0 += 8) GROUP8(j0, e);
            uhi = e;
        }
    }
#undef GROUP8

    int n = b*PP + (int)__float_as_uint(q.w);   // original point id
    #pragma unroll
    for (int s = 0; s < KK; ++s)
        g_ku[(size_t)s*NN + n] = top[s];
}

// ---------------- kernel 2: eig + dense-basis spline conv ----------------
// grid: 256 (8 x 32 chunks), 128 threads
// smem: sx/sy/sz[4096] (48K) + basis scratch (32256) + W float4 (16000)
__global__ void __launch_bounds__(128, 2) k_feat(
    const float* __restrict__ pos,
    const float* __restrict__ Wsp,
    const float* __restrict__ root,
    const float* __restrict__ bias)
{
    extern __shared__ char smch[];
    float* sx = (float*)smch;                 // 4096
    float* sy = sx + PP;
    float* sz = sy + PP;
    float* sbas = (float*)(smch + 49152);                 // 128*63 floats
    float4* swW = (float4*)(smch + 49152 + 32256);        // 1000 float4

    int b     = blockIdx.x >> 5;
    int chunk = blockIdx.x & 31;
    int tid   = threadIdx.x;
    int lane  = tid & 31;
    int wid   = tid >> 5;

    for (int i = tid; i < PP; i += 128) {
        const float* p = pos + (size_t)(b*PP + i)*3;
        sx[i] = p[0]; sy[i] = p[1]; sz[i] = p[2];
    }
    const float4* Wsp4 = (const float4*)Wsp;
    for (int i = tid; i < 125*8; i += 128) swW[i] = Wsp4[i];
    __syncthreads();

    int sg = chunk*128 + tid;
    int n  = b*PP + sg;
    float qx = sx[sg], qy = sy[sg], qz = sz[sg];

    // ---- load sorted top-20 (complete; no merge needed) ----
    int nb[KK];
    #pragma unroll
    for (int s = 0; s < KK; ++s)
        nb[s] = (int)(g_ku[(size_t)s*NN + n] & 0xFFFFFFFFu);

    // ---- covariance over the 10 nearest ----
    float cxx=0,cxy=0,cxz=0,cyy=0,cyz=0,czz=0;
    #pragma unroll
    for (int l = 0; l < LL; ++l) {
        int j = nb[l];
        float dx = sx[j]-qx, dy = sy[j]-qy, dz = sz[j]-qz;
        cxx += dx*dx; cxy += dx*dy; cxz += dx*dz;
        cyy += dy*dy; cyz += dy*dz; czz += dz*dz;
    }

    // ---- eigenvectors ----
    float v1x,v1y,v1z,l1;
    power_iter(cxx,cxy,cxz,cyy,cyz,czz, v1x,v1y,v1z,l1);
    float m00 = cxx - l1*v1x*v1x, m01 = cxy - l1*v1x*v1y, m02 = cxz - l1*v1x*v1z;
    float m11 = cyy - l1*v1y*v1y, m12 = cyz - l1*v1y*v1z, m22 = czz - l1*v1z*v1z;
    float v2x,v2y,v2z,l2;
    power_iter(m00,m01,m02,m11,m12,m22, v2x,v2y,v2z,l2);
    float v3x = v1y*v2z - v1z*v2y;
    float v3y = v1z*v2x - v1x*v2z;
    float v3z = v1x*v2y - v1y*v2x;
    float n3  = sqrtf(v3x*v3x + v3y*v3y + v3z*v3z);
    float i3  = 1.0f / (n3 + 1e-12f);
    v3x *= i3; v3y *= i3; v3z *= i3;

    // ---- pass A: sign and max-abs ----
    float ssum = 0.f, mx12 = 0.f, mx3 = 0.f;
    #pragma unroll
    for (int k = 0; k < KK; ++k) {
        int j = nb[k];
        float dx = sx[j]-qx, dy = sy[j]-qy, dz = sz[j]-qz;
        float d1 = dx*v1x + dy*v1y + dz*v1z;
        float d2 = dx*v2x + dy*v2y + dz*v2z;
        float d3 = dx*v3x + dy*v3y + dz*v3z;
        ssum += d3;
        mx12 = fmaxf(mx12, fmaxf(fabsf(d1), fabsf(d2)));
        mx3  = fmaxf(mx3, fabsf(d3));
    }
    float sgn    = (ssum > 0.f) ? 1.f : ((ssum < 0.f) ? -1.f : 0.f);
    float maxabs = (sgn != 0.f) ? fmaxf(mx12, mx3) : mx12;
    float rm     = 1.0f / maxabs;

    // ---- pass B: dense-basis spline conv in 2 cell-range passes ----
    float msg[FF];
    #pragma unroll
    for (int f = 0; f < FF; ++f) msg[f] = 0.f;

    int off = tid*63;

    #pragma unroll 1
    for (int pass = 0; pass < 2; ++pass) {
        int lo    = pass ? 63 : 0;
        int width = pass ? 62 : 63;

        for (int c = 0; c < 63; ++c) sbas[off + c] = 0.f;

        #pragma unroll 1
        for (int k = 0; k < KK; ++k) {
            int j = nb[k];
            float dx = sx[j]-qx, dy = sy[j]-qy, dz = sz[j]-qz;
            float d0 = dx*v1x + dy*v1y + dz*v1z;
            float d1 = dx*v2x + dy*v2y + dz*v2z;
            float d2 = (dx*v3x + dy*v3y + dz*v3z) * sgn;

            float vv0 = (d0*rm*0.5f + 0.5f)*4.f;
            float vv1 = (d1*rm*0.5f + 0.5f)*4.f;
            float vv2 = (d2*rm*0.5f + 0.5f)*4.f;
            float fl0 = floorf(vv0), fl1 = floorf(vv1), fl2 = floorf(vv2);
            float fr0 = vv0-fl0, fr1 = vv1-fl1, fr2 = vv2-fl2;
            int i0 = (int)fl0, i1 = (int)fl1, i2 = (int)fl2;

            int ia0 = min(max(i0,  0),4), ib0 = min(max(i0+1,0),4);
            int ia1 = min(max(i1,  0),4), ib1 = min(max(i1+1,0),4);
            int ia2 = min(max(i2,  0),4), ib2 = min(max(i2+1,0),4);
            float wa0 = 1.f-fr0, wb0 = fr0;
            float wa1 = 1.f-fr1, wb1 = fr1;
            float wa2 = 1.f-fr2, wb2 = fr2;

            #pragma unroll
            for (int s8 = 0; s8 < 8; ++s8) {
                int bit0 = (s8>>2)&1, bit1 = (s8>>1)&1, bit2 = s8&1;
                float bas = (bit0?wb0:wa0) * (bit1?wb1:wa1) * (bit2?wb2:wa2);
                int j0 = bit0?ib0:ia0, j1 = bit1?ib1:ia1, j2 = bit2?ib2:ia2;
                int cell = (j0*KSS + j1)*KSS + j2;
                int loc  = cell - lo;
                if (loc >= 0 && loc < width)
                    sbas[off + loc] += bas;
            }
        }

        #pragma unroll 4
        for (int c = 0; c < width; ++c) {
            float bb = sbas[off + c];
            int cell = lo + c;
            #pragma unroll
            for (int f4 = 0; f4 < 8; ++f4) {
                float4 w = swW[cell*8 + f4];
                msg[4*f4+0] += bb * w.x;
                msg[4*f4+1] += bb * w.y;
                msg[4*f4+2] += bb * w.z;
                msg[4*f4+3] += bb * w.w;
            }
        }
    }

    // ---- node output + fused batch-stat accumulation ----
    float keepS = 0.f, keepS2 = 0.f;
    #pragma unroll
    for (int f = 0; f < FF; ++f) {
        float v = msg[f] * (1.0f/(float)KK) + root[f] + bias[f];
        g_node[(size_t)n*FF + f] = v;
        float s = v, s2 = v*v;
        #pragma unroll
        for (int o2 = 16; o2; o2 >>= 1) {
            s  += __shfl_xor_sync(0xFFFFFFFFu, s,  o2);
            s2 += __shfl_xor_sync(0xFFFFFFFFu, s2, o2);
        }
        if (lane == f) { keepS = s; keepS2 = s2; }
    }
    g_v3[n*3+0] = v3x; g_v3[n*3+1] = v3y; g_v3[n*3+2] = v3z;

    __shared__ float blkS[4][FF], blkS2[4][FF];
    blkS[wid][lane] = keepS; blkS2[wid][lane] = keepS2;
    __syncthreads();
    if (wid == 0) {
        float tS  = blkS[0][lane]  + blkS[1][lane]  + blkS[2][lane]  + blkS[3][lane];
        float tS2 = blkS2[0][lane] + blkS2[1][lane] + blkS2[2][lane] + blkS2[3][lane];
        atomicAdd(&g_acc[lane],      (double)tS);
        atomicAdd(&g_acc[FF + lane], (double)tS2);
    }
}

// ---------------- kernel 3: BN-fold + sigmoid + reshape-mean (fin fused) ------
__global__ void k_ys(const float* __restrict__ gamma, const float* __restrict__ beta)
{
    __shared__ float sa[FF], sb[FF];
    int r = blockIdx.x >> 5;
    int j = blockIdx.x & 31;
    int tid = threadIdx.x;

    if (tid < FF) {
        double mu  = g_acc[tid] / (double)NN;
        double var = g_acc[FF+tid] / (double)NN - mu*mu;
        float istd = (float)(1.0 / sqrt(var + 1e-5));
        float a = gamma[tid] * istd;
        sa[tid] = a;
        sb[tid] = beta[tid] - (float)mu * a;
    }
    __syncthreads();

    float sum = 0.f;
    #pragma unroll 4
    for (int p = tid; p < PP; p += 128) {
        int flat = r*(PP*FF) + p*FF + j;
        int nn   = flat / 96;
        int rem  = flat - nn*96;
        int fch  = rem / 3;
        int c    = rem - fch*3;
        float x  = g_node[(size_t)nn*FF + fch];
        float xb = fmaf(sa[fch], x, sb[fch]);
        float o  = xb * g_v3[nn*3 + c];
        sum += __fdividef(1.f, 1.f + __expf(-o));
    }
    __shared__ float red[128];
    red[tid] = sum;
    __syncthreads();
    for (int off = 64; off; off >>= 1) {
        if (tid < off) red[tid] += red[tid+off];
        __syncthreads();
    }
    if (tid == 0) g_ys[r*FF + j] = red[0] / (float)PP;
}

// ---------------- kernel 4: MLP head + log_softmax (one block per row) --------
__global__ void k_head(
    const float* __restrict__ W1, const float* __restrict__ b1,
    const float* __restrict__ W2, const float* __restrict__ b2,
    float* __restrict__ out)
{
    __shared__ float ys[FF];
    __shared__ float y1[256];
    __shared__ float part[8][NCLS];
    __shared__ float zz[NCLS];
    __shared__ float s_lse;
    int r = blockIdx.x, tid = threadIdx.x;   // 320 threads

    if (tid < FF) ys[tid] = g_ys[r*FF + tid];
    __syncthreads();

    if (tid < 256) {
        float acc = b1[tid];
        #pragma unroll
        for (int f = 0; f < FF; ++f) acc = fmaf(ys[f], W1[f*256 + tid], acc);
        y1[tid] = acc > 0.f ? acc : expm1f(acc);
    }
    __syncthreads();

    {
        int c  = tid % NCLS;
        int sgm = tid / NCLS;     // 0..7
        float acc = 0.f;
        #pragma unroll
        for (int h = 0; h < 32; ++h) acc = fmaf(y1[sgm*32 + h], W2[(sgm*32+h)*NCLS + c], acc);
        part[sgm][c] = acc;
    }
    __syncthreads();

    if (tid < NCLS) {
        float acc = b2[tid];
        #pragma unroll
        for (int s = 0; s < 8; ++s) acc += part[s][tid];
        zz[tid] = acc;
    }
    __syncthreads();

    if (tid == 0) {
        float mx = -3.4e38f;
        for (int c = 0; c < NCLS; ++c) mx = fmaxf(mx, zz[c]);
        float se = 0.f;
        for (int c = 0; c < NCLS; ++c) se += expf(zz[c] - mx);
        s_lse = mx + logf(se);
    }
    __syncthreads();
    if (tid < NCLS) out[r*NCLS + tid] = zz[tid] - s_lse;
}

// ---------------- launch ----------------
extern "C" void kernel_launch(void* const* d_in, const int* in_sizes, int n_in,
                              void* d_out, int out_size)
{
    const float* pos   = (const float*)d_in[0];
    const float* Wsp   = (const float*)d_in[1];
    const float* root  = (const float*)d_in[2];
    const float* bias  = (const float*)d_in[3];
    const float* gamma = (const float*)d_in[4];
    const float* beta  = (const float*)d_in[5];
    const float* W1    = (const float*)d_in[6];
    const float* b1    = (const float*)d_in[7];
    const float* W2    = (const float*)d_in[8];
    const float* b2    = (const float*)d_in[9];
    float* out = (float*)d_out;

    size_t smem_knn  = (size_t)PP*16;               // 65,536 B
    size_t smem_feat = 49152 + 32256 + 16000;       // 97,408 B
    cudaFuncSetAttribute(k_knn,  cudaFuncAttributeMaxDynamicSharedMemorySize, (int)smem_knn);
    cudaFuncSetAttribute(k_feat, cudaFuncAttributeMaxDynamicSharedMemorySize, (int)smem_feat);

    k_sort <<<BB, 1024>>>(pos);
    k_knn  <<<BB*32, 128, smem_knn>>>();
    k_feat <<<BB*32, 128, smem_feat>>>(pos, Wsp, root, bias);
    k_ys   <<<R24*FF, 128>>>(gamma, beta);
    k_head <<<R24, 320>>>(W1, b1, W2, b2, out);
}